// round 8
// baseline (speedup 1.0000x reference)
#include <cuda_runtime.h>
#include <math.h>

// Problem constants
#define BB 4
#define SS 256
#define NN 512
#define RR 32
#define LL (NN * RR)          // 16384 output samples per batch
#define NCHUNK 8
#define S_PER_CHUNK (SS / NCHUNK)  // 32
#define NE 513                // extended segments: head(1) + 511 mids + tail
#define NQ2 257               // ceil(513/2) segment-pairs per batch

// Reference-matching constants
#define TWO_PI_D 6.283185307179586
#define CF_F  ((float)(TWO_PI_D / 44100.0))
#define CMOD_F ((float)TWO_PI_D)
#define INV_CMOD_F ((float)(1.0 / (double)((float)TWO_PI_D)))

// Scratch
__device__ float4 d_tab[BB * SS * NE];       // {base_mod, g, dg/64, a}
__device__ float  d_da [BB * SS * NE];       // a_{i+1}-a_i

// ---------------------------------------------------------------------------
// double-float helpers (all-fp32 compensated arithmetic)
// ---------------------------------------------------------------------------
__device__ __forceinline__ float2 two_sum(float a, float b) {
    float s  = a + b;
    float bb = s - a;
    float e  = (a - (s - bb)) + (b - bb);
    return make_float2(s, e);
}
__device__ __forceinline__ float2 df_add(float2 a, float2 b) {
    float2 s = two_sum(a.x, b.x);
    float lo = s.y + (a.y + b.y);
    float hi = s.x + lo;
    lo = lo - (hi - s.x);
    return make_float2(hi, lo);
}

// ---------------------------------------------------------------------------
// Kernel 1: df-precision prefix of omegas -> per-segment fp32 table.
// Base phase stored already reduced mod fl32(2*pi), so the hot-loop phase
// argument stays in [0, ~30) and MUFU.SIN's HW range reduction costs only
// ~|x|*2^-23 ~ 4e-6 rad of phase error.
// ---------------------------------------------------------------------------
__global__ void k_base(const float* __restrict__ freq,
                       const float* __restrict__ amp) {
    int seq  = blockIdx.x;
    int i    = threadIdx.x;
    int lane = i & 31;
    int wid  = i >> 5;

    float f = freq[seq * NN + i];
    float a = amp [seq * NN + i];

    float g_hi = f * CF_F;
    float g_lo = fmaf(f, CF_F, -g_hi);      // exact product tail
    float2 x = make_float2(g_hi, g_lo);

    #pragma unroll
    for (int off = 1; off < 32; off <<= 1) {
        float yh = __shfl_up_sync(0xFFFFFFFFu, x.x, off);
        float yl = __shfl_up_sync(0xFFFFFFFFu, x.y, off);
        if (lane >= off) x = df_add(x, make_float2(yh, yl));
    }

    __shared__ float2 wsum[16];
    if (lane == 31) wsum[wid] = x;
    __syncthreads();
    if (wid == 0) {
        float2 y = (lane < 16) ? wsum[lane] : make_float2(0.0f, 0.0f);
        #pragma unroll
        for (int off = 1; off < 16; off <<= 1) {
            float zh = __shfl_up_sync(0xFFFFFFFFu, y.x, off);
            float zl = __shfl_up_sync(0xFFFFFFFFu, y.y, off);
            if (lane >= off) y = df_add(y, make_float2(zh, zl));
        }
        if (lane < 16) wsum[lane] = y;
    }
    __syncthreads();
    float2 Q = x;
    if (wid > 0) Q = df_add(Q, wsum[wid - 1]);

    float2 Q32  = make_float2(32.0f * Q.x, 32.0f * Q.y);
    float2 g16n = make_float2(-16.0f * g_hi, -16.0f * g_lo);
    float2 P = df_add(Q32, g16n);

    float q = floorf(P.x * INV_CMOD_F);
    float m = fmaf(-q, CMOD_F, P.x) + P.y;

    float fnext = (i < NN - 1) ? freq[seq * NN + i + 1] : f;
    float anext = (i < NN - 1) ? amp [seq * NN + i + 1] : a;
    float dg64 = (i < NN - 1) ? (fnext * CF_F - g_hi) * (1.0f / 64.0f) : 0.0f;
    float da   = (i < NN - 1) ? (anext - a) : 0.0f;

    size_t tb = (size_t)seq * NE;
    d_tab[tb + i + 1] = make_float4(m, g_hi, dg64, a);
    d_da [tb + i + 1] = da;
    if (i == 0) {
        d_tab[tb] = make_float4(0.0f, g_hi, 0.0f, a);
        d_da [tb] = 0.0f;
    }
}

// ---------------------------------------------------------------------------
// Kernel 2: synthesis. Block = 256 thr = 8 sine-chunks (warps) x
// [2 segments x 16 lanes]; 2 t-samples per thread per table load.
// Batch-of-4 sines: 8 front-batched LDGs, then 8 independent chains of
// just 2 FMA -> MUFU.SIN -> FMA (no explicit mod: phase in [0,~30) is fed
// to MUFU.SIN's hardware range reduction directly).
// Fixed-order smem reduction => bitwise deterministic.
// ---------------------------------------------------------------------------
__global__ void __launch_bounds__(256, 4) k_main(float* __restrict__ out) {
    int tid  = threadIdx.x;
    int c    = tid >> 5;            // sine chunk 0..7
    int lane = tid & 31;
    int seg2 = lane >> 4;           // local segment 0..1
    int jg   = lane & 15;           // samples j = jg, jg+16

    int q = blockIdx.x % NQ2;       // segment pair
    int b = blockIdx.x / NQ2;
    int e = 2 * q + seg2;           // extended segment index (may be 513)
    int ec = (e > NE - 1) ? (NE - 1) : e;   // clamp for safe loads

    float u0 = (float)(jg + 1);
    float u1 = u0 + 16.0f;
    float s0 = u0 * u0, s1 = u1 * u1;
    float w0 = (float)(2 * jg + 1) * (1.0f / 64.0f);
    float w1 = w0 + 0.5f;

    size_t rowbase = (size_t)(b * SS + c * S_PER_CHUNK) * NE + ec;
    const float4* tp = d_tab + rowbase;
    const float*  dp = d_da  + rowbase;

    float a0 = 0.0f, a1 = 0.0f;

    #pragma unroll
    for (int k0 = 0; k0 < S_PER_CHUNK; k0 += 4) {
        float4 v0 = __ldg(tp);
        float4 v1 = __ldg(tp + NE);
        float4 v2 = __ldg(tp + 2 * NE);
        float4 v3 = __ldg(tp + 3 * NE);
        float  d0 = __ldg(dp);
        float  d1 = __ldg(dp + NE);
        float  d2 = __ldg(dp + 2 * NE);
        float  d3 = __ldg(dp + 3 * NE);
        tp += 4 * NE; dp += 4 * NE;

        float p00 = fmaf(s0, v0.z, fmaf(u0, v0.y, v0.x));
        float p01 = fmaf(s1, v0.z, fmaf(u1, v0.y, v0.x));
        float p10 = fmaf(s0, v1.z, fmaf(u0, v1.y, v1.x));
        float p11 = fmaf(s1, v1.z, fmaf(u1, v1.y, v1.x));
        float p20 = fmaf(s0, v2.z, fmaf(u0, v2.y, v2.x));
        float p21 = fmaf(s1, v2.z, fmaf(u1, v2.y, v2.x));
        float p30 = fmaf(s0, v3.z, fmaf(u0, v3.y, v3.x));
        float p31 = fmaf(s1, v3.z, fmaf(u1, v3.y, v3.x));

        float m00 = fmaf(w0, d0, v0.w);
        float m01 = fmaf(w1, d0, v0.w);
        float m10 = fmaf(w0, d1, v1.w);
        float m11 = fmaf(w1, d1, v1.w);
        float m20 = fmaf(w0, d2, v2.w);
        float m21 = fmaf(w1, d2, v2.w);
        float m30 = fmaf(w0, d3, v3.w);
        float m31 = fmaf(w1, d3, v3.w);

        a0 = fmaf(m00, __sinf(p00), a0);
        a1 = fmaf(m01, __sinf(p01), a1);
        a0 = fmaf(m10, __sinf(p10), a0);
        a1 = fmaf(m11, __sinf(p11), a1);
        a0 = fmaf(m20, __sinf(p20), a0);
        a1 = fmaf(m21, __sinf(p21), a1);
        a0 = fmaf(m30, __sinf(p30), a0);
        a1 = fmaf(m31, __sinf(p31), a1);
    }

    __shared__ float sred[NCHUNK][2 * 33];
    int base = seg2 * 33 + jg;
    sred[c][base     ] = a0;
    sred[c][base + 16] = a1;
    __syncthreads();

    if (tid < 64) {
        int e_loc = tid >> 5;           // 0..1
        int j     = tid & 31;
        int e_out = 2 * q + e_loc;
        float s = 0.0f;
        #pragma unroll
        for (int cc = 0; cc < NCHUNK; cc++) s += sred[cc][e_loc * 33 + j];

        bool valid = (e_out <= NE - 1);
        if (e_out == 0 || e_out == NE - 1) valid = valid && (j < 16);
        if (valid) {
            int t = (e_out == 0) ? j : 16 + 32 * (e_out - 1) + j;
            out[b * LL + t] = s;
        }
    }
}

// ---------------------------------------------------------------------------
extern "C" void kernel_launch(void* const* d_in, const int* in_sizes, int n_in,
                              void* d_out, int out_size) {
    const float* freq = (const float*)d_in[0];
    const float* amp  = (const float*)d_in[1];
    float* out = (float*)d_out;

    k_base<<<BB * SS, NN>>>(freq, amp);        // 1024 blocks x 512
    k_main<<<BB * NQ2, 256>>>(out);            // 1028 blocks x 256
}

// round 9
// speedup vs baseline: 1.0171x; 1.0171x over previous
#include <cuda_runtime.h>
#include <math.h>

// Problem constants
#define BB 4
#define SS 256
#define NN 512
#define RR 32
#define LL (NN * RR)          // 16384 output samples per batch
#define NCHUNK 8
#define S_PER_CHUNK (SS / NCHUNK)  // 32
#define NE 513                // extended segments: head(1) + 511 mids + tail
#define NQ2 257               // ceil(513/2) segment-pairs per batch

// Reference-matching constants
#define TWO_PI_D 6.283185307179586
#define CF_F  ((float)(TWO_PI_D / 44100.0))
#define CMOD_F ((float)TWO_PI_D)
#define INV_CMOD_F ((float)(1.0 / (double)((float)TWO_PI_D)))

// Scratch
__device__ float4 d_tab[BB * SS * NE];       // {base_mod, g, dg/64, a}
__device__ float  d_da [BB * SS * NE];       // a_{i+1}-a_i

// ---------------------------------------------------------------------------
// double-float helpers (all-fp32 compensated arithmetic)
// ---------------------------------------------------------------------------
__device__ __forceinline__ float2 two_sum(float a, float b) {
    float s  = a + b;
    float bb = s - a;
    float e  = (a - (s - bb)) + (b - bb);
    return make_float2(s, e);
}
__device__ __forceinline__ float2 df_add(float2 a, float2 b) {
    float2 s = two_sum(a.x, b.x);
    float lo = s.y + (a.y + b.y);
    float hi = s.x + lo;
    lo = lo - (hi - s.x);
    return make_float2(hi, lo);
}

// ---------------------------------------------------------------------------
// Kernel 1: df-precision prefix of omegas -> per-segment fp32 table.
// Base phase stored reduced mod fl32(2*pi): hot-loop phase stays in [0,~30),
// where MUFU.SIN's HW range reduction adds only ~4e-6 rad of error.
// ---------------------------------------------------------------------------
__global__ void k_base(const float* __restrict__ freq,
                       const float* __restrict__ amp) {
    int seq  = blockIdx.x;
    int i    = threadIdx.x;
    int lane = i & 31;
    int wid  = i >> 5;

    float f = freq[seq * NN + i];
    float a = amp [seq * NN + i];

    float g_hi = f * CF_F;
    float g_lo = fmaf(f, CF_F, -g_hi);      // exact product tail
    float2 x = make_float2(g_hi, g_lo);

    #pragma unroll
    for (int off = 1; off < 32; off <<= 1) {
        float yh = __shfl_up_sync(0xFFFFFFFFu, x.x, off);
        float yl = __shfl_up_sync(0xFFFFFFFFu, x.y, off);
        if (lane >= off) x = df_add(x, make_float2(yh, yl));
    }

    __shared__ float2 wsum[16];
    if (lane == 31) wsum[wid] = x;
    __syncthreads();
    if (wid == 0) {
        float2 y = (lane < 16) ? wsum[lane] : make_float2(0.0f, 0.0f);
        #pragma unroll
        for (int off = 1; off < 16; off <<= 1) {
            float zh = __shfl_up_sync(0xFFFFFFFFu, y.x, off);
            float zl = __shfl_up_sync(0xFFFFFFFFu, y.y, off);
            if (lane >= off) y = df_add(y, make_float2(zh, zl));
        }
        if (lane < 16) wsum[lane] = y;
    }
    __syncthreads();
    float2 Q = x;
    if (wid > 0) Q = df_add(Q, wsum[wid - 1]);

    float2 Q32  = make_float2(32.0f * Q.x, 32.0f * Q.y);
    float2 g16n = make_float2(-16.0f * g_hi, -16.0f * g_lo);
    float2 P = df_add(Q32, g16n);

    float q = floorf(P.x * INV_CMOD_F);
    float m = fmaf(-q, CMOD_F, P.x) + P.y;

    float fnext = (i < NN - 1) ? freq[seq * NN + i + 1] : f;
    float anext = (i < NN - 1) ? amp [seq * NN + i + 1] : a;
    float dg64 = (i < NN - 1) ? (fnext * CF_F - g_hi) * (1.0f / 64.0f) : 0.0f;
    float da   = (i < NN - 1) ? (anext - a) : 0.0f;

    size_t tb = (size_t)seq * NE;
    d_tab[tb + i + 1] = make_float4(m, g_hi, dg64, a);
    d_da [tb + i + 1] = da;
    if (i == 0) {
        d_tab[tb] = make_float4(0.0f, g_hi, 0.0f, a);
        d_da [tb] = 0.0f;
    }
}

// ---------------------------------------------------------------------------
// Kernel 2: synthesis with SMEM-staged table.
// Block covers one (batch, segment-pair) for all 256 sines. The 10KB slice
// {tab, da} for the pair is staged into shared memory once, then the
// fully-unrolled 32-sine loop runs out of LDS with immediate offsets
// (29-cyc latency, broadcast, zero bank conflicts) instead of L2 LDGs.
// Fixed-order smem reduction => bitwise deterministic.
// ---------------------------------------------------------------------------
__global__ void __launch_bounds__(256, 4) k_main(float* __restrict__ out) {
    int tid  = threadIdx.x;
    int c    = tid >> 5;            // sine chunk 0..7
    int lane = tid & 31;
    int seg2 = lane >> 4;           // local segment 0..1
    int jg   = lane & 15;           // samples j = jg, jg+16

    int q = blockIdx.x % NQ2;       // segment pair
    int b = blockIdx.x / NQ2;
    int e0  = 2 * q;
    int e0c = (e0     > NE - 1) ? (NE - 1) : e0;
    int e1c = (e0 + 1 > NE - 1) ? (NE - 1) : (e0 + 1);

    // ---- stage the block's table slice: 256 sines x 2 segments ----
    __shared__ float4 stab[SS][2];  // 8 KB
    __shared__ float  sda [SS][2];  // 2 KB
    {
        const float4* row  = d_tab + (size_t)(b * SS + tid) * NE;
        const float*  drow = d_da  + (size_t)(b * SS + tid) * NE;
        stab[tid][0] = __ldg(row  + e0c);
        stab[tid][1] = __ldg(row  + e1c);
        sda [tid][0] = __ldg(drow + e0c);
        sda [tid][1] = __ldg(drow + e1c);
    }
    __syncthreads();

    float u0 = (float)(jg + 1);
    float u1 = u0 + 16.0f;
    float s0 = u0 * u0, s1 = u1 * u1;
    float w0 = (float)(2 * jg + 1) * (1.0f / 64.0f);
    float w1 = w0 + 0.5f;

    int sbase = c * S_PER_CHUNK;
    float a0 = 0.0f, a1 = 0.0f;

    #pragma unroll
    for (int k = 0; k < S_PER_CHUNK; k += 4) {
        float4 v0 = stab[sbase + k    ][seg2];
        float4 v1 = stab[sbase + k + 1][seg2];
        float4 v2 = stab[sbase + k + 2][seg2];
        float4 v3 = stab[sbase + k + 3][seg2];
        float  d0 = sda [sbase + k    ][seg2];
        float  d1 = sda [sbase + k + 1][seg2];
        float  d2 = sda [sbase + k + 2][seg2];
        float  d3 = sda [sbase + k + 3][seg2];

        float p00 = fmaf(s0, v0.z, fmaf(u0, v0.y, v0.x));
        float p01 = fmaf(s1, v0.z, fmaf(u1, v0.y, v0.x));
        float p10 = fmaf(s0, v1.z, fmaf(u0, v1.y, v1.x));
        float p11 = fmaf(s1, v1.z, fmaf(u1, v1.y, v1.x));
        float p20 = fmaf(s0, v2.z, fmaf(u0, v2.y, v2.x));
        float p21 = fmaf(s1, v2.z, fmaf(u1, v2.y, v2.x));
        float p30 = fmaf(s0, v3.z, fmaf(u0, v3.y, v3.x));
        float p31 = fmaf(s1, v3.z, fmaf(u1, v3.y, v3.x));

        float m00 = fmaf(w0, d0, v0.w);
        float m01 = fmaf(w1, d0, v0.w);
        float m10 = fmaf(w0, d1, v1.w);
        float m11 = fmaf(w1, d1, v1.w);
        float m20 = fmaf(w0, d2, v2.w);
        float m21 = fmaf(w1, d2, v2.w);
        float m30 = fmaf(w0, d3, v3.w);
        float m31 = fmaf(w1, d3, v3.w);

        a0 = fmaf(m00, __sinf(p00), a0);
        a1 = fmaf(m01, __sinf(p01), a1);
        a0 = fmaf(m10, __sinf(p10), a0);
        a1 = fmaf(m11, __sinf(p11), a1);
        a0 = fmaf(m20, __sinf(p20), a0);
        a1 = fmaf(m21, __sinf(p21), a1);
        a0 = fmaf(m30, __sinf(p30), a0);
        a1 = fmaf(m31, __sinf(p31), a1);
    }

    __shared__ float sred[NCHUNK][2 * 33];
    int base = seg2 * 33 + jg;
    sred[c][base     ] = a0;
    sred[c][base + 16] = a1;
    __syncthreads();

    if (tid < 64) {
        int e_loc = tid >> 5;           // 0..1
        int j     = tid & 31;
        int e_out = 2 * q + e_loc;
        float s = 0.0f;
        #pragma unroll
        for (int cc = 0; cc < NCHUNK; cc++) s += sred[cc][e_loc * 33 + j];

        bool valid = (e_out <= NE - 1);
        if (e_out == 0 || e_out == NE - 1) valid = valid && (j < 16);
        if (valid) {
            int t = (e_out == 0) ? j : 16 + 32 * (e_out - 1) + j;
            out[b * LL + t] = s;
        }
    }
}

// ---------------------------------------------------------------------------
extern "C" void kernel_launch(void* const* d_in, const int* in_sizes, int n_in,
                              void* d_out, int out_size) {
    const float* freq = (const float*)d_in[0];
    const float* amp  = (const float*)d_in[1];
    float* out = (float*)d_out;

    k_base<<<BB * SS, NN>>>(freq, amp);        // 1024 blocks x 512
    k_main<<<BB * NQ2, 256>>>(out);            // 1028 blocks x 256
}